// round 4
// baseline (speedup 1.0000x reference)
#include <cuda_runtime.h>
#include <math.h>

#define BB 2
#define HH 16
#define SS 2048
#define DD 64
#define BM 64
#define BN 64
#define PAD 4
#define LDP (DD + PAD)        // 68
#define SCALE 0.125f          // 1/sqrt(64)
#define EPS_ADJ 1e-9f

// scratch for avAp [B,H,D,D]
__device__ float g_avAp[BB * HH * DD * DD];

// ---------------------------------------------------------------------------
// Kernel 1: avAp = a @ ( (iswiglu(W@A + b) + eps) ^ pw ) + ba   per (b,h)
// one block per (b,h), 256 threads, 4x4 register tiles on a 16x16 thread grid
// ---------------------------------------------------------------------------
__global__ __launch_bounds__(256) void avap_kernel(
    const float* __restrict__ A,  // [B,H,D,D]
    const float* __restrict__ W,  // [H,D,D]
    const float* __restrict__ b,  // [H,D,D]
    const float* __restrict__ pw, // [H,D,D]
    const float* __restrict__ aM, // [H,D,D]
    const float* __restrict__ ba) // [H,D,D]
{
    extern __shared__ float smem[];
    float (*sW)[LDP] = (float (*)[LDP])smem;                       // [64][68]
    float (*sA)[LDP] = (float (*)[LDP])(smem + DD * LDP);          // [64][68]
    float (*sT)[LDP] = (float (*)[LDP])(smem + 2 * DD * LDP);      // [64][68]

    const int bh = blockIdx.x;
    const int h  = bh % HH;
    const int tid = threadIdx.x;
    const int ty = tid >> 4, tx = tid & 15;

    const float* Wp = W + h * DD * DD;
    const float* Ap = A + bh * DD * DD;

    for (int i = tid; i < DD * DD; i += 256) {
        int r = i >> 6, c = i & 63;
        sW[r][c] = Wp[i];
        sA[r][c] = Ap[i];
    }
    __syncthreads();

    // x = W @ A
    float acc[4][4] = {};
    for (int k = 0; k < DD; k++) {
        float wv[4];
        #pragma unroll
        for (int i = 0; i < 4; i++) wv[i] = sW[ty * 4 + i][k];
        float4 a4 = *(const float4*)&sA[k][tx * 4];
        float av[4] = {a4.x, a4.y, a4.z, a4.w};
        #pragma unroll
        for (int i = 0; i < 4; i++)
            #pragma unroll
            for (int j = 0; j < 4; j++)
                acc[i][j] = fmaf(wv[i], av[j], acc[i][j]);
    }
    // iswiglu(x)+eps then ^pw
    #pragma unroll
    for (int i = 0; i < 4; i++) {
        #pragma unroll
        for (int j = 0; j < 4; j++) {
            int r = ty * 4 + i, c = tx * 4 + j;
            float x  = acc[i][j] + b[h * DD * DD + r * DD + c];
            float sg = 1.0f / (1.0f + expf(-x));
            float aw = x * x * sg + EPS_ADJ;
            float p  = pw[h * DD * DD + r * DD + c];
            sT[r][c] = powf(aw, p);
        }
    }
    __syncthreads();   // sT visible; sW free

    const float* ap2 = aM + h * DD * DD;
    for (int i = tid; i < DD * DD; i += 256) sW[i >> 6][i & 63] = ap2[i];
    __syncthreads();

    // avAp = a @ Ap + ba
    float acc2[4][4] = {};
    for (int k = 0; k < DD; k++) {
        float wv[4];
        #pragma unroll
        for (int i = 0; i < 4; i++) wv[i] = sW[ty * 4 + i][k];
        float4 t4 = *(const float4*)&sT[k][tx * 4];
        float tv[4] = {t4.x, t4.y, t4.z, t4.w};
        #pragma unroll
        for (int i = 0; i < 4; i++)
            #pragma unroll
            for (int j = 0; j < 4; j++)
                acc2[i][j] = fmaf(wv[i], tv[j], acc2[i][j]);
    }
    #pragma unroll
    for (int i = 0; i < 4; i++) {
        #pragma unroll
        for (int j = 0; j < 4; j++) {
            int r = ty * 4 + i, c = tx * 4 + j;
            g_avAp[bh * DD * DD + r * DD + c] =
                acc2[i][j] + ba[h * DD * DD + r * DD + c];
        }
    }
}

// ---------------------------------------------------------------------------
// Kernel 2: fused causal flash attention, fp32
//   Q_tile = Hin_tile @ avAp,  Ep = Q K^T * scale, online softmax, O = P V
// grid: (S/BM, B*H), 256 threads, 4x4 microtiles
// ---------------------------------------------------------------------------
__global__ __launch_bounds__(256) void attn_kernel(
    const float* __restrict__ Hin,
    const float* __restrict__ Hk,
    const float* __restrict__ Hv,
    float* __restrict__ Out)
{
    extern __shared__ float smem[];
    float (*sQ )[LDP] = (float (*)[LDP])smem;                        // [64][68]
    float (*sKT)[LDP] = (float (*)[LDP])(smem + 1 * DD * LDP);       // [64][68] (d-major)
    float (*sV )[LDP] = (float (*)[LDP])(smem + 2 * DD * LDP);       // [64][68]
    float (*sS )[LDP] = (float (*)[LDP])(smem + 3 * DD * LDP);       // [64][68]
    float* sM     = smem + 4 * DD * LDP;
    float* sL     = sM + BM;
    float* sAlpha = sL + BM;

    const int qt  = blockIdx.x;
    const int bh  = blockIdx.y;
    const int tid = threadIdx.x;
    const int ty  = tid >> 4, tx = tid & 15;

    const float* hin = Hin + (size_t)bh * SS * DD;
    const float* hk  = Hk  + (size_t)bh * SS * DD;
    const float* hv  = Hv  + (size_t)bh * SS * DD;
    const float* av  = g_avAp + bh * DD * DD;
    float* out = Out + (size_t)bh * SS * DD;

    // ---- load Hin tile (into sS temp) and avAp (into sV temp) ----
    for (int i = tid; i < BM * DD / 4; i += 256) {
        int r = i >> 4, c = (i & 15) << 2;
        *(float4*)&sS[r][c] = *(const float4*)&hin[(size_t)(qt * BM + r) * DD + c];
        *(float4*)&sV[r][c] = *(const float4*)&av[r * DD + c];
    }
    __syncthreads();

    // ---- Q = Hin_tile @ avAp ----
    float qacc[4][4] = {};
    for (int d = 0; d < DD; d++) {
        float hvv[4];
        #pragma unroll
        for (int i = 0; i < 4; i++) hvv[i] = sS[ty * 4 + i][d];
        float4 m4 = *(const float4*)&sV[d][tx * 4];
        float mv[4] = {m4.x, m4.y, m4.z, m4.w};
        #pragma unroll
        for (int i = 0; i < 4; i++)
            #pragma unroll
            for (int j = 0; j < 4; j++)
                qacc[i][j] = fmaf(hvv[i], mv[j], qacc[i][j]);
    }
    #pragma unroll
    for (int i = 0; i < 4; i++)
        #pragma unroll
        for (int j = 0; j < 4; j++)
            sQ[ty * 4 + i][tx * 4 + j] = qacc[i][j];

    if (tid < BM) { sM[tid] = -3.0e38f; sL[tid] = 0.0f; }
    __syncthreads();

    float oacc[4][4] = {};
    const int nkt = qt + 1;   // causal

    for (int kt = 0; kt < nkt; kt++) {
        // load K (transposed) and V tiles
        for (int i = tid; i < BN * DD / 4; i += 256) {
            int r = i >> 4, c = (i & 15) << 2;
            float4 k4 = *(const float4*)&hk[(size_t)(kt * BN + r) * DD + c];
            sKT[c + 0][r] = k4.x;
            sKT[c + 1][r] = k4.y;
            sKT[c + 2][r] = k4.z;
            sKT[c + 3][r] = k4.w;
            *(float4*)&sV[r][c] = *(const float4*)&hv[(size_t)(kt * BN + r) * DD + c];
        }
        __syncthreads();

        // S = Q K^T * scale (+ causal mask)
        float sacc[4][4] = {};
        for (int d = 0; d < DD; d++) {
            float qv[4];
            #pragma unroll
            for (int i = 0; i < 4; i++) qv[i] = sQ[ty * 4 + i][d];
            float4 k4 = *(const float4*)&sKT[d][tx * 4];
            float kv[4] = {k4.x, k4.y, k4.z, k4.w};
            #pragma unroll
            for (int i = 0; i < 4; i++)
                #pragma unroll
                for (int j = 0; j < 4; j++)
                    sacc[i][j] = fmaf(qv[i], kv[j], sacc[i][j]);
        }
        #pragma unroll
        for (int i = 0; i < 4; i++) {
            int qrow = qt * BM + ty * 4 + i;
            float4 s4;
            float* sp = (float*)&s4;
            #pragma unroll
            for (int j = 0; j < 4; j++) {
                int kcol = kt * BN + tx * 4 + j;
                float v = sacc[i][j] * SCALE;
                sp[j] = (kcol > qrow) ? -1.0e9f : v;
            }
            *(float4*)&sS[ty * 4 + i][tx * 4] = s4;
        }
        __syncthreads();

        // online softmax, one thread per row
        if (tid < BM) {
            float mOld = sM[tid];
            float mNew = mOld;
            #pragma unroll 8
            for (int k = 0; k < BN; k++) mNew = fmaxf(mNew, sS[tid][k]);
            float alpha = expf(mOld - mNew);
            float lsum = 0.0f;
            #pragma unroll 8
            for (int k = 0; k < BN; k++) {
                float p = expf(sS[tid][k] - mNew);
                sS[tid][k] = p;
                lsum += p;
            }
            sL[tid] = sL[tid] * alpha + lsum;
            sM[tid] = mNew;
            sAlpha[tid] = alpha;
        }
        __syncthreads();

        // O = O*alpha + P @ V
        float al[4];
        #pragma unroll
        for (int i = 0; i < 4; i++) al[i] = sAlpha[ty * 4 + i];
        #pragma unroll
        for (int i = 0; i < 4; i++)
            #pragma unroll
            for (int j = 0; j < 4; j++)
                oacc[i][j] *= al[i];
        for (int k = 0; k < BN; k++) {
            float pv[4];
            #pragma unroll
            for (int i = 0; i < 4; i++) pv[i] = sS[ty * 4 + i][k];
            float4 v4 = *(const float4*)&sV[k][tx * 4];
            float vv[4] = {v4.x, v4.y, v4.z, v4.w};
            #pragma unroll
            for (int i = 0; i < 4; i++)
                #pragma unroll
                for (int j = 0; j < 4; j++)
                    oacc[i][j] = fmaf(pv[i], vv[j], oacc[i][j]);
        }
        __syncthreads();
    }

    // write output (normalized)
    #pragma unroll
    for (int i = 0; i < 4; i++) {
        float inv = 1.0f / sL[ty * 4 + i];
        float4 o4 = make_float4(oacc[i][0] * inv, oacc[i][1] * inv,
                                oacc[i][2] * inv, oacc[i][3] * inv);
        *(float4*)&out[(size_t)(qt * BM + ty * 4 + i) * DD + tx * 4] = o4;
    }
}

// ---------------------------------------------------------------------------
extern "C" void kernel_launch(void* const* d_in, const int* in_sizes, int n_in,
                              void* d_out, int out_size)
{
    const float* Hin  = (const float*)d_in[0];
    const float* Hk   = (const float*)d_in[1];
    const float* Hv   = (const float*)d_in[2];
    const float* A    = (const float*)d_in[3];
    // d_in[4] = mask (causal, implemented analytically)
    const float* W    = (const float*)d_in[5];
    const float* b    = (const float*)d_in[6];
    const float* pw   = (const float*)d_in[7];
    const float* aM   = (const float*)d_in[8];
    const float* ba   = (const float*)d_in[9];
    float* Out = (float*)d_out;

    const int smem1 = 3 * DD * LDP * sizeof(float);                 // 52224 B
    const int smem2 = (4 * DD * LDP + 3 * BM) * sizeof(float);      // 70400 B

    cudaFuncSetAttribute(avap_kernel, cudaFuncAttributeMaxDynamicSharedMemorySize, smem1);
    cudaFuncSetAttribute(attn_kernel, cudaFuncAttributeMaxDynamicSharedMemorySize, smem2);

    avap_kernel<<<BB * HH, 256, smem1>>>(A, W, b, pw, aM, ba);
    attn_kernel<<<dim3(SS / BM, BB * HH), 256, smem2>>>(Hin, Hk, Hv, Out);
}

// round 7
// speedup vs baseline: 1.0092x; 1.0092x over previous
#include <cuda_runtime.h>
#include <math.h>

#define BB 2
#define HH 16
#define SS 2048
#define DD 64
#define BM 64
#define BN 64
#define PAD 4
#define LDP (DD + PAD)        // 68
#define SCALE 0.125f          // 1/sqrt(64)
#define EPS_ADJ 1e-9f

// scratch for avAp [B,H,D,D]
__device__ float g_avAp[BB * HH * DD * DD];

// ---------------------------------------------------------------------------
// Kernel 1: avAp = a @ ( (iswiglu(W@A + b) + eps) ^ pw ) + ba   per (b,h)
// one block per (b,h), 256 threads, 4x4 register tiles on a 16x16 thread grid
// ---------------------------------------------------------------------------
__global__ __launch_bounds__(256) void avap_kernel(
    const float* __restrict__ A,  // [B,H,D,D]
    const float* __restrict__ W,  // [H,D,D]
    const float* __restrict__ b,  // [H,D,D]
    const float* __restrict__ pw, // [H,D,D]
    const float* __restrict__ aM, // [H,D,D]
    const float* __restrict__ ba) // [H,D,D]
{
    extern __shared__ float smem[];
    float (*sW)[LDP] = (float (*)[LDP])smem;                       // [64][68]
    float (*sA)[LDP] = (float (*)[LDP])(smem + DD * LDP);          // [64][68]
    float (*sT)[LDP] = (float (*)[LDP])(smem + 2 * DD * LDP);      // [64][68]

    const int bh = blockIdx.x;
    const int h  = bh % HH;
    const int tid = threadIdx.x;
    const int ty = tid >> 4, tx = tid & 15;

    const float* Wp = W + h * DD * DD;
    const float* Ap = A + bh * DD * DD;

    for (int i = tid; i < DD * DD; i += 256) {
        int r = i >> 6, c = i & 63;
        sW[r][c] = Wp[i];
        sA[r][c] = Ap[i];
    }
    __syncthreads();

    // x = W @ A
    float acc[4][4] = {};
    for (int k = 0; k < DD; k++) {
        float wv[4];
        #pragma unroll
        for (int i = 0; i < 4; i++) wv[i] = sW[ty * 4 + i][k];
        float4 a4 = *(const float4*)&sA[k][tx * 4];
        float av[4] = {a4.x, a4.y, a4.z, a4.w};
        #pragma unroll
        for (int i = 0; i < 4; i++)
            #pragma unroll
            for (int j = 0; j < 4; j++)
                acc[i][j] = fmaf(wv[i], av[j], acc[i][j]);
    }
    // iswiglu(x)+eps then ^pw
    #pragma unroll
    for (int i = 0; i < 4; i++) {
        #pragma unroll
        for (int j = 0; j < 4; j++) {
            int r = ty * 4 + i, c = tx * 4 + j;
            float x  = acc[i][j] + b[h * DD * DD + r * DD + c];
            float sg = 1.0f / (1.0f + expf(-x));
            float aw = x * x * sg + EPS_ADJ;
            float p  = pw[h * DD * DD + r * DD + c];
            sT[r][c] = powf(aw, p);
        }
    }
    __syncthreads();   // sT visible; sW free

    const float* ap2 = aM + h * DD * DD;
    for (int i = tid; i < DD * DD; i += 256) sW[i >> 6][i & 63] = ap2[i];
    __syncthreads();

    // avAp = a @ Ap + ba
    float acc2[4][4] = {};
    for (int k = 0; k < DD; k++) {
        float wv[4];
        #pragma unroll
        for (int i = 0; i < 4; i++) wv[i] = sW[ty * 4 + i][k];
        float4 t4 = *(const float4*)&sT[k][tx * 4];
        float tv[4] = {t4.x, t4.y, t4.z, t4.w};
        #pragma unroll
        for (int i = 0; i < 4; i++)
            #pragma unroll
            for (int j = 0; j < 4; j++)
                acc2[i][j] = fmaf(wv[i], tv[j], acc2[i][j]);
    }
    #pragma unroll
    for (int i = 0; i < 4; i++) {
        #pragma unroll
        for (int j = 0; j < 4; j++) {
            int r = ty * 4 + i, c = tx * 4 + j;
            g_avAp[bh * DD * DD + r * DD + c] =
                acc2[i][j] + ba[h * DD * DD + r * DD + c];
        }
    }
}

// ---------------------------------------------------------------------------
// Kernel 2: fused causal flash attention, fp32
//   Q_tile = Hin_tile @ avAp,  Ep = Q K^T * scale, online softmax, O = P V
// grid: (S/BM, B*H), 256 threads, 4x4 microtiles
// ---------------------------------------------------------------------------
__global__ __launch_bounds__(256) void attn_kernel(
    const float* __restrict__ Hin,
    const float* __restrict__ Hk,
    const float* __restrict__ Hv,
    float* __restrict__ Out)
{
    extern __shared__ float smem[];
    float (*sQ )[LDP] = (float (*)[LDP])smem;                        // [64][68]
    float (*sKT)[LDP] = (float (*)[LDP])(smem + 1 * DD * LDP);       // [64][68] (d-major)
    float (*sV )[LDP] = (float (*)[LDP])(smem + 2 * DD * LDP);       // [64][68]
    float (*sS )[LDP] = (float (*)[LDP])(smem + 3 * DD * LDP);       // [64][68]
    float* sM     = smem + 4 * DD * LDP;
    float* sL     = sM + BM;
    float* sAlpha = sL + BM;

    const int qt  = blockIdx.x;
    const int bh  = blockIdx.y;
    const int tid = threadIdx.x;
    const int ty  = tid >> 4, tx = tid & 15;

    const float* hin = Hin + (size_t)bh * SS * DD;
    const float* hk  = Hk  + (size_t)bh * SS * DD;
    const float* hv  = Hv  + (size_t)bh * SS * DD;
    const float* av  = g_avAp + bh * DD * DD;
    float* out = Out + (size_t)bh * SS * DD;

    // ---- load Hin tile (into sS temp) and avAp (into sV temp) ----
    for (int i = tid; i < BM * DD / 4; i += 256) {
        int r = i >> 4, c = (i & 15) << 2;
        *(float4*)&sS[r][c] = *(const float4*)&hin[(size_t)(qt * BM + r) * DD + c];
        *(float4*)&sV[r][c] = *(const float4*)&av[r * DD + c];
    }
    __syncthreads();

    // ---- Q = Hin_tile @ avAp ----
    float qacc[4][4] = {};
    for (int d = 0; d < DD; d++) {
        float hvv[4];
        #pragma unroll
        for (int i = 0; i < 4; i++) hvv[i] = sS[ty * 4 + i][d];
        float4 m4 = *(const float4*)&sV[d][tx * 4];
        float mv[4] = {m4.x, m4.y, m4.z, m4.w};
        #pragma unroll
        for (int i = 0; i < 4; i++)
            #pragma unroll
            for (int j = 0; j < 4; j++)
                qacc[i][j] = fmaf(hvv[i], mv[j], qacc[i][j]);
    }
    #pragma unroll
    for (int i = 0; i < 4; i++)
        #pragma unroll
        for (int j = 0; j < 4; j++)
            sQ[ty * 4 + i][tx * 4 + j] = qacc[i][j];

    if (tid < BM) { sM[tid] = -3.0e38f; sL[tid] = 0.0f; }
    __syncthreads();

    float oacc[4][4] = {};
    const int nkt = qt + 1;   // causal

    for (int kt = 0; kt < nkt; kt++) {
        // load K (transposed) and V tiles
        for (int i = tid; i < BN * DD / 4; i += 256) {
            int r = i >> 4, c = (i & 15) << 2;
            float4 k4 = *(const float4*)&hk[(size_t)(kt * BN + r) * DD + c];
            sKT[c + 0][r] = k4.x;
            sKT[c + 1][r] = k4.y;
            sKT[c + 2][r] = k4.z;
            sKT[c + 3][r] = k4.w;
            *(float4*)&sV[r][c] = *(const float4*)&hv[(size_t)(kt * BN + r) * DD + c];
        }
        __syncthreads();

        // S = Q K^T * scale (+ causal mask)
        float sacc[4][4] = {};
        for (int d = 0; d < DD; d++) {
            float qv[4];
            #pragma unroll
            for (int i = 0; i < 4; i++) qv[i] = sQ[ty * 4 + i][d];
            float4 k4 = *(const float4*)&sKT[d][tx * 4];
            float kv[4] = {k4.x, k4.y, k4.z, k4.w};
            #pragma unroll
            for (int i = 0; i < 4; i++)
                #pragma unroll
                for (int j = 0; j < 4; j++)
                    sacc[i][j] = fmaf(qv[i], kv[j], sacc[i][j]);
        }
        #pragma unroll
        for (int i = 0; i < 4; i++) {
            int qrow = qt * BM + ty * 4 + i;
            float4 s4;
            float* sp = (float*)&s4;
            #pragma unroll
            for (int j = 0; j < 4; j++) {
                int kcol = kt * BN + tx * 4 + j;
                float v = sacc[i][j] * SCALE;
                sp[j] = (kcol > qrow) ? -1.0e9f : v;
            }
            *(float4*)&sS[ty * 4 + i][tx * 4] = s4;
        }
        __syncthreads();

        // online softmax, one thread per row
        if (tid < BM) {
            float mOld = sM[tid];
            float mNew = mOld;
            #pragma unroll 8
            for (int k = 0; k < BN; k++) mNew = fmaxf(mNew, sS[tid][k]);
            float alpha = expf(mOld - mNew);
            float lsum = 0.0f;
            #pragma unroll 8
            for (int k = 0; k < BN; k++) {
                float p = expf(sS[tid][k] - mNew);
                sS[tid][k] = p;
                lsum += p;
            }
            sL[tid] = sL[tid] * alpha + lsum;
            sM[tid] = mNew;
            sAlpha[tid] = alpha;
        }
        __syncthreads();

        // O = O*alpha + P @ V
        float al[4];
        #pragma unroll
        for (int i = 0; i < 4; i++) al[i] = sAlpha[ty * 4 + i];
        #pragma unroll
        for (int i = 0; i < 4; i++)
            #pragma unroll
            for (int j = 0; j < 4; j++)
                oacc[i][j] *= al[i];
        for (int k = 0; k < BN; k++) {
            float pv[4];
            #pragma unroll
            for (int i = 0; i < 4; i++) pv[i] = sS[ty * 4 + i][k];
            float4 v4 = *(const float4*)&sV[k][tx * 4];
            float vv[4] = {v4.x, v4.y, v4.z, v4.w};
            #pragma unroll
            for (int i = 0; i < 4; i++)
                #pragma unroll
                for (int j = 0; j < 4; j++)
                    oacc[i][j] = fmaf(pv[i], vv[j], oacc[i][j]);
        }
        __syncthreads();
    }

    // write output (normalized)
    #pragma unroll
    for (int i = 0; i < 4; i++) {
        float inv = 1.0f / sL[ty * 4 + i];
        float4 o4 = make_float4(oacc[i][0] * inv, oacc[i][1] * inv,
                                oacc[i][2] * inv, oacc[i][3] * inv);
        *(float4*)&out[(size_t)(qt * BM + ty * 4 + i) * DD + tx * 4] = o4;
    }
}

// ---------------------------------------------------------------------------
extern "C" void kernel_launch(void* const* d_in, const int* in_sizes, int n_in,
                              void* d_out, int out_size)
{
    const float* Hin  = (const float*)d_in[0];
    const float* Hk   = (const float*)d_in[1];
    const float* Hv   = (const float*)d_in[2];
    const float* A    = (const float*)d_in[3];
    // d_in[4] = mask (causal, implemented analytically)
    const float* W    = (const float*)d_in[5];
    const float* b    = (const float*)d_in[6];
    const float* pw   = (const float*)d_in[7];
    const float* aM   = (const float*)d_in[8];
    const float* ba   = (const float*)d_in[9];
    float* Out = (float*)d_out;

    const int smem1 = 3 * DD * LDP * sizeof(float);                 // 52224 B
    const int smem2 = (4 * DD * LDP + 3 * BM) * sizeof(float);      // 70400 B

    cudaFuncSetAttribute(avap_kernel, cudaFuncAttributeMaxDynamicSharedMemorySize, smem1);
    cudaFuncSetAttribute(attn_kernel, cudaFuncAttributeMaxDynamicSharedMemorySize, smem2);

    avap_kernel<<<BB * HH, 256, smem1>>>(A, W, b, pw, aM, ba);
    attn_kernel<<<dim3(SS / BM, BB * HH), 256, smem2>>>(Hin, Hk, Hv, Out);
}

// round 13
// speedup vs baseline: 2.5687x; 2.5454x over previous
#include <cuda_runtime.h>
#include <cuda_bf16.h>
#include <math.h>
#include <stdint.h>

#define BB 2
#define HH 16
#define SS 2048
#define DD 64
#define BH (BB*HH)
#define LDP 68
#define EPS_ADJ 1e-9f
// 1/sqrt(64) * log2(e) folded into Q so softmax uses exp2
#define QK_SCALE 0.18033688011112042f

// ------------------------------ device scratch ------------------------------
__device__ float         g_avAp[BH * DD * DD];
__device__ __nv_bfloat16 g_VTh[BH*DD*SS], g_VTl[BH*DD*SS];   // [bh][d][s]

// single extern-shared symbol for the whole TU
extern __shared__ char dsmem[];

// ------------------------------ helpers ---------------------------------
__device__ __forceinline__ float ex2f(float x) {
    float y; asm("ex2.approx.ftz.f32 %0, %1;" : "=f"(y) : "f"(x)); return y;
}
__device__ __forceinline__ uint32_t pack_bf16x2(__nv_bfloat16 e0, __nv_bfloat16 e1) {
    __nv_bfloat162 t = __halves2bfloat162(e0, e1);   // e0 -> low 16 bits
    return *reinterpret_cast<uint32_t*>(&t);
}
__device__ __forceinline__ void split2(float v, __nv_bfloat16& h, __nv_bfloat16& l) {
    h = __float2bfloat16_rn(v);
    l = __float2bfloat16_rn(v - __bfloat162float(h));
}

// D(16x8,f32) += A(16x16 bf16, row) * B(8x16 bf16, "col" = K rows)
#define MMA16816(c, a, b0, b1) \
    asm volatile("mma.sync.aligned.m16n8k16.row.col.f32.bf16.bf16.f32 " \
        "{%0,%1,%2,%3}, {%4,%5,%6,%7}, {%8,%9}, {%0,%1,%2,%3};" \
        : "+f"((c)[0]), "+f"((c)[1]), "+f"((c)[2]), "+f"((c)[3]) \
        : "r"((a)[0]), "r"((a)[1]), "r"((a)[2]), "r"((a)[3]), "r"(b0), "r"(b1))

// ---------------------------------------------------------------------------
// Kernel 1: avAp = a @ ((iswiglu(W@A+b)+eps)^pw) + ba   (verified)
// ---------------------------------------------------------------------------
__global__ __launch_bounds__(256) void avap_kernel(
    const float* __restrict__ A, const float* __restrict__ W,
    const float* __restrict__ b, const float* __restrict__ pw,
    const float* __restrict__ aM, const float* __restrict__ ba)
{
    float* smem = (float*)dsmem;
    float (*sW)[LDP] = (float (*)[LDP])smem;
    float (*sA)[LDP] = (float (*)[LDP])(smem + DD * LDP);
    float (*sT)[LDP] = (float (*)[LDP])(smem + 2 * DD * LDP);
    const int bh = blockIdx.x, h = bh % HH;
    const int tid = threadIdx.x, ty = tid >> 4, tx = tid & 15;
    const float* Wp = W + h * DD * DD;
    const float* Ap = A + bh * DD * DD;

    for (int i = tid; i < DD * DD; i += 256) {
        int r = i >> 6, c = i & 63;
        sW[r][c] = Wp[i]; sA[r][c] = Ap[i];
    }
    __syncthreads();
    float acc[4][4] = {};
    for (int k = 0; k < DD; k++) {
        float wv[4];
        #pragma unroll
        for (int i = 0; i < 4; i++) wv[i] = sW[ty*4+i][k];
        float4 a4 = *(const float4*)&sA[k][tx*4];
        float av[4] = {a4.x, a4.y, a4.z, a4.w};
        #pragma unroll
        for (int i = 0; i < 4; i++)
            #pragma unroll
            for (int j = 0; j < 4; j++) acc[i][j] = fmaf(wv[i], av[j], acc[i][j]);
    }
    #pragma unroll
    for (int i = 0; i < 4; i++)
        #pragma unroll
        for (int j = 0; j < 4; j++) {
            int r = ty*4+i, c = tx*4+j;
            float x = acc[i][j] + b[h*DD*DD + r*DD + c];
            float sg = 1.0f / (1.0f + expf(-x));
            float aw = x * x * sg + EPS_ADJ;
            sT[r][c] = powf(aw, pw[h*DD*DD + r*DD + c]);
        }
    __syncthreads();
    const float* ap2 = aM + h * DD * DD;
    for (int i = tid; i < DD * DD; i += 256) sW[i>>6][i&63] = ap2[i];
    __syncthreads();
    float acc2[4][4] = {};
    for (int k = 0; k < DD; k++) {
        float wv[4];
        #pragma unroll
        for (int i = 0; i < 4; i++) wv[i] = sW[ty*4+i][k];
        float4 t4 = *(const float4*)&sT[k][tx*4];
        float tv[4] = {t4.x, t4.y, t4.z, t4.w};
        #pragma unroll
        for (int i = 0; i < 4; i++)
            #pragma unroll
            for (int j = 0; j < 4; j++) acc2[i][j] = fmaf(wv[i], tv[j], acc2[i][j]);
    }
    #pragma unroll
    for (int i = 0; i < 4; i++)
        #pragma unroll
        for (int j = 0; j < 4; j++) {
            int r = ty*4+i, c = tx*4+j;
            g_avAp[bh*DD*DD + r*DD + c] = acc2[i][j] + ba[h*DD*DD + r*DD + c];
        }
}

// ---------------------------------------------------------------------------
// Kernel 2: V transpose + 2-way bf16 split:  VT[bh][d][s]
// ---------------------------------------------------------------------------
__global__ __launch_bounds__(256) void vprep_kernel(const float* __restrict__ V)
{
    __shared__ float tl[64][65];
    const int st = blockIdx.x, bh = blockIdx.y;
    const int tid = threadIdx.x;
    const float* vp = V + ((size_t)bh * SS + st * 64) * DD;
    for (int i = tid; i < 4096; i += 256) tl[i >> 6][i & 63] = vp[i];
    __syncthreads();
    for (int i = tid; i < 4096; i += 256) {
        int d = i >> 6, s = i & 63;
        __nv_bfloat16 h, l; split2(tl[s][d], h, l);
        size_t o = ((size_t)bh * DD + d) * SS + st * 64 + s;
        g_VTh[o] = h; g_VTl[o] = l;
    }
}

// ---------------------------------------------------------------------------
// Kernel 3: fused flash attention on HMMA (mma.sync bf16, split-2 x3 combos)
// CTA = 64 q-rows, 128 threads (4 warps x 16 rows). Grid (32 qt, 32 bh).
// smem: sQh,sQl,sKh,sKl,sVh,sVl each [64][72] bf16 (9216 B) -> 55296 B
// ---------------------------------------------------------------------------
#define ROWW 36   // uint32 words per row (72 bf16)
#define ATTN_SMEM 55296

__global__ __launch_bounds__(128) void attn_mma_kernel(
    const float* __restrict__ Hin, const float* __restrict__ Hk,
    float* __restrict__ Out)
{
    uint32_t* wQh = (uint32_t*)(dsmem);
    uint32_t* wQl = (uint32_t*)(dsmem + 9216);
    uint32_t* wKh = (uint32_t*)(dsmem + 18432);
    uint32_t* wKl = (uint32_t*)(dsmem + 27648);
    uint32_t* wVh = (uint32_t*)(dsmem + 36864);
    uint32_t* wVl = (uint32_t*)(dsmem + 46080);

    const int tid  = threadIdx.x;
    const int lane = tid & 31, wid = tid >> 5;
    const int qt = (int)(gridDim.x - 1 - blockIdx.x);   // big tiles first
    const int bh = blockIdx.y;
    const int g  = lane >> 2;       // fragment row within 8
    const int q4 = lane & 3;        // fragment col group

    // ---- stage Hin tile + avAp (in K/V region), compute Q, split to sQ ----
    {
        float* fH  = (float*)(dsmem + 18432);    // [64][68]
        float* fAv = (float*)(dsmem + 35840);    // [64][68]
        for (int i = tid; i < 1024; i += 128) {
            int r = i >> 4, c = (i & 15) << 2;
            *(float4*)&fH[r*68 + c]  =
                *(const float4*)&Hin[((size_t)bh*SS + qt*64 + r)*64 + c];
            *(float4*)&fAv[r*68 + c] =
                *(const float4*)&g_avAp[bh*4096 + r*64 + c];
        }
        __syncthreads();
        const int ty = tid >> 4, tx = tid & 15;   // rows ty*8.., cols tx*4..
        float acc[8][4] = {};
        for (int k = 0; k < 64; k++) {
            float4 av = *(const float4*)&fAv[k*68 + tx*4];
            #pragma unroll
            for (int i = 0; i < 8; i++) {
                float hv = fH[(ty*8+i)*68 + k];
                acc[i][0] = fmaf(hv, av.x, acc[i][0]);
                acc[i][1] = fmaf(hv, av.y, acc[i][1]);
                acc[i][2] = fmaf(hv, av.z, acc[i][2]);
                acc[i][3] = fmaf(hv, av.w, acc[i][3]);
            }
        }
        __syncthreads();   // all reads of fH/fAv done before Q overwrites... (wQ separate region, but keep ordering tight)
        #pragma unroll
        for (int i = 0; i < 8; i++) {
            int row = ty*8 + i;
            #pragma unroll
            for (int jp = 0; jp < 2; jp++) {
                float v0 = acc[i][jp*2]   * QK_SCALE;
                float v1 = acc[i][jp*2+1] * QK_SCALE;
                __nv_bfloat16 h0,l0,h1,l1;
                split2(v0,h0,l0); split2(v1,h1,l1);
                wQh[row*ROWW + tx*2 + jp] = pack_bf16x2(h0,h1);
                wQl[row*ROWW + tx*2 + jp] = pack_bf16x2(l0,l1);
            }
        }
        __syncthreads();   // Q done; fH/fAv region free for K/V staging
    }

    float m_run[2] = {-1e30f, -1e30f};
    float l_run[2] = {0.0f, 0.0f};
    float oacc[8][4] = {};

    for (int kt = 0; kt <= qt; kt++) {
        // ---- stage K tile (split inline from fp32) ----
        for (int i = tid; i < 1024; i += 128) {
            int r = i >> 4, c = (i & 15) << 2;
            float4 v = *(const float4*)&Hk[((size_t)bh*SS + kt*64 + r)*64 + c];
            __nv_bfloat16 h0,l0,h1,l1,h2,l2,h3,l3;
            split2(v.x,h0,l0); split2(v.y,h1,l1);
            split2(v.z,h2,l2); split2(v.w,h3,l3);
            int w = r*ROWW + (i & 15)*2;
            wKh[w] = pack_bf16x2(h0,h1); wKh[w+1] = pack_bf16x2(h2,h3);
            wKl[w] = pack_bf16x2(l0,l1); wKl[w+1] = pack_bf16x2(l2,l3);
        }
        // ---- stage VT tile (already split in global, bf16) ----
        // 64 d-rows x 8 uint4-chunks (16 bf16 each) = 512 iterations
        for (int i = tid; i < 512; i += 128) {
            int d = i >> 3, s8 = (i & 7) << 3;
            size_t off = ((size_t)bh*64 + d)*SS + (size_t)kt*64 + s8;
            *(uint4*)((char*)wVh + d*144 + s8*2) = *(const uint4*)(g_VTh + off);
            *(uint4*)((char*)wVl + d*144 + s8*2) = *(const uint4*)(g_VTl + off);
        }
        __syncthreads();

        // ---- S = Q K^T : 3 split combos (hh, hl, lh) ----
        float sacc[8][4] = {};
        const int arow = wid*16 + g;
        #pragma unroll
        for (int kk = 0; kk < 4; kk++) {
            const int base = kk*8 + q4;
            uint32_t aH[4], aL[4];
            aH[0] = wQh[arow*ROWW + base];       aH[1] = wQh[(arow+8)*ROWW + base];
            aH[2] = wQh[arow*ROWW + base + 4];   aH[3] = wQh[(arow+8)*ROWW + base + 4];
            aL[0] = wQl[arow*ROWW + base];       aL[1] = wQl[(arow+8)*ROWW + base];
            aL[2] = wQl[arow*ROWW + base + 4];   aL[3] = wQl[(arow+8)*ROWW + base + 4];
            #pragma unroll
            for (int n = 0; n < 8; n++) {
                const int brow = n*8 + g;
                uint32_t bH0 = wKh[brow*ROWW + base], bH1 = wKh[brow*ROWW + base + 4];
                uint32_t bL0 = wKl[brow*ROWW + base], bL1 = wKl[brow*ROWW + base + 4];
                MMA16816(sacc[n], aH, bH0, bH1);
                MMA16816(sacc[n], aH, bL0, bL1);
                MMA16816(sacc[n], aL, bH0, bH1);
            }
        }

        // ---- causal mask (diagonal block only) ----
        if (kt == qt) {
            #pragma unroll
            for (int n = 0; n < 8; n++)
                #pragma unroll
                for (int c = 0; c < 4; c++) {
                    int col = n*8 + q4*2 + (c & 1);
                    int row = wid*16 + g + ((c >> 1) << 3);
                    if (col > row) sacc[n][c] = -1e30f;
                }
        }

        // ---- online softmax (thread owns 2 rows; 4 lanes share a row) ----
        float mt0 = -1e30f, mt1 = -1e30f;
        #pragma unroll
        for (int n = 0; n < 8; n++) {
            mt0 = fmaxf(mt0, fmaxf(sacc[n][0], sacc[n][1]));
            mt1 = fmaxf(mt1, fmaxf(sacc[n][2], sacc[n][3]));
        }
        mt0 = fmaxf(mt0, __shfl_xor_sync(0xFFFFFFFFu, mt0, 1));
        mt0 = fmaxf(mt0, __shfl_xor_sync(0xFFFFFFFFu, mt0, 2));
        mt1 = fmaxf(mt1, __shfl_xor_sync(0xFFFFFFFFu, mt1, 1));
        mt1 = fmaxf(mt1, __shfl_xor_sync(0xFFFFFFFFu, mt1, 2));
        float mN0 = fmaxf(m_run[0], mt0), mN1 = fmaxf(m_run[1], mt1);
        float al0 = ex2f(m_run[0] - mN0), al1 = ex2f(m_run[1] - mN1);
        m_run[0] = mN0; m_run[1] = mN1;

        float ls0 = 0.0f, ls1 = 0.0f;
        #pragma unroll
        for (int n = 0; n < 8; n++) {
            float p0 = ex2f(sacc[n][0] - mN0);
            float p1 = ex2f(sacc[n][1] - mN0);
            float p2 = ex2f(sacc[n][2] - mN1);
            float p3 = ex2f(sacc[n][3] - mN1);
            sacc[n][0] = p0; sacc[n][1] = p1; sacc[n][2] = p2; sacc[n][3] = p3;
            ls0 += p0 + p1; ls1 += p2 + p3;
            oacc[n][0] *= al0; oacc[n][1] *= al0;
            oacc[n][2] *= al1; oacc[n][3] *= al1;
        }
        l_run[0] = l_run[0]*al0 + ls0;
        l_run[1] = l_run[1]*al1 + ls1;

        // ---- O += P V : 3 split combos; P packed in-register as A frags ----
        #pragma unroll
        for (int kk = 0; kk < 4; kk++) {
            uint32_t aH[4], aL[4];
            #pragma unroll
            for (int t = 0; t < 2; t++) {
                int nn = 2*kk + t;
                __nv_bfloat16 h0,l0,h1,l1;
                split2(sacc[nn][0], h0,l0); split2(sacc[nn][1], h1,l1);
                aH[2*t]   = pack_bf16x2(h0,h1); aL[2*t]   = pack_bf16x2(l0,l1);
                split2(sacc[nn][2], h0,l0); split2(sacc[nn][3], h1,l1);
                aH[2*t+1] = pack_bf16x2(h0,h1); aL[2*t+1] = pack_bf16x2(l0,l1);
            }
            const int base = kk*8 + q4;
            #pragma unroll
            for (int n = 0; n < 8; n++) {
                const int brow = n*8 + g;
                uint32_t bH0 = wVh[brow*ROWW + base], bH1 = wVh[brow*ROWW + base + 4];
                uint32_t bL0 = wVl[brow*ROWW + base], bL1 = wVl[brow*ROWW + base + 4];
                MMA16816(oacc[n], aH, bH0, bH1);
                MMA16816(oacc[n], aH, bL0, bL1);
                MMA16816(oacc[n], aL, bH0, bH1);
            }
        }
        __syncthreads();   // protect K/V smem before next staging
    }

    // ---- epilogue: reduce l across the 4 lanes of each row, normalize ----
    float lt0 = l_run[0];
    lt0 += __shfl_xor_sync(0xFFFFFFFFu, lt0, 1);
    lt0 += __shfl_xor_sync(0xFFFFFFFFu, lt0, 2);
    float lt1 = l_run[1];
    lt1 += __shfl_xor_sync(0xFFFFFFFFu, lt1, 1);
    lt1 += __shfl_xor_sync(0xFFFFFFFFu, lt1, 2);
    float inv0 = 1.0f / lt0, inv1 = 1.0f / lt1;

    const int row0 = qt*64 + wid*16 + g;
    const int row1 = row0 + 8;
    #pragma unroll
    for (int n = 0; n < 8; n++) {
        int col = n*8 + q4*2;
        float2 o0 = make_float2(oacc[n][0]*inv0, oacc[n][1]*inv0);
        float2 o1 = make_float2(oacc[n][2]*inv1, oacc[n][3]*inv1);
        *(float2*)&Out[((size_t)bh*SS + row0)*64 + col] = o0;
        *(float2*)&Out[((size_t)bh*SS + row1)*64 + col] = o1;
    }
}

// ---------------------------------------------------------------------------
extern "C" void kernel_launch(void* const* d_in, const int* in_sizes, int n_in,
                              void* d_out, int out_size)
{
    const float* Hin = (const float*)d_in[0];
    const float* Hk  = (const float*)d_in[1];
    const float* Hv  = (const float*)d_in[2];
    const float* A   = (const float*)d_in[3];
    // d_in[4] = mask (causal, analytic)
    const float* W   = (const float*)d_in[5];
    const float* b   = (const float*)d_in[6];
    const float* pw  = (const float*)d_in[7];
    const float* aM  = (const float*)d_in[8];
    const float* ba  = (const float*)d_in[9];
    float* Out = (float*)d_out;

    const int smem1 = 3 * DD * LDP * sizeof(float);   // 52224
    cudaFuncSetAttribute(avap_kernel, cudaFuncAttributeMaxDynamicSharedMemorySize, smem1);
    cudaFuncSetAttribute(attn_mma_kernel, cudaFuncAttributeMaxDynamicSharedMemorySize, ATTN_SMEM);

    avap_kernel<<<BH, 256, smem1>>>(A, W, b, pw, aM, ba);
    vprep_kernel<<<dim3(SS / 64, BH), 256>>>(Hv);
    attn_mma_kernel<<<dim3(SS / 64, BH), 128, ATTN_SMEM>>>(Hin, Hk, Out);
}

// round 16
// speedup vs baseline: 2.7659x; 1.0768x over previous
#include <cuda_runtime.h>
#include <cuda_bf16.h>
#include <math.h>
#include <stdint.h>

#define BB 2
#define HH 16
#define SS 2048
#define DD 64
#define BH (BB*HH)
#define LDP 68
#define EPS_ADJ 1e-9f
// 1/sqrt(64) * log2(e) folded into Q so softmax uses exp2
#define QK_SCALE 0.18033688011112042f

// ------------------------------ device scratch ------------------------------
__device__ float         g_avAp[BH * DD * DD];
__device__ __nv_bfloat16 g_Kh[BH*SS*DD],  g_Kl[BH*SS*DD];    // [bh][s][d]
__device__ __nv_bfloat16 g_VTh[BH*DD*SS], g_VTl[BH*DD*SS];   // [bh][d][s]

// single extern-shared symbol for the whole TU
extern __shared__ char dsmem[];

// ------------------------------ helpers ---------------------------------
__device__ __forceinline__ float ex2f(float x) {
    float y; asm("ex2.approx.ftz.f32 %0, %1;" : "=f"(y) : "f"(x)); return y;
}
__device__ __forceinline__ uint32_t smem_to_u32(const void* p) {
    uint32_t a;
    asm("{ .reg .u64 t; cvta.to.shared.u64 t, %1; cvt.u32.u64 %0, t; }" : "=r"(a) : "l"(p));
    return a;
}
__device__ __forceinline__ uint32_t pack_bf16x2(__nv_bfloat16 e0, __nv_bfloat16 e1) {
    __nv_bfloat162 t = __halves2bfloat162(e0, e1);   // e0 -> low 16 bits
    return *reinterpret_cast<uint32_t*>(&t);
}
__device__ __forceinline__ void split2(float v, __nv_bfloat16& h, __nv_bfloat16& l) {
    h = __float2bfloat16_rn(v);
    l = __float2bfloat16_rn(v - __bfloat162float(h));
}

#define CP_ASYNC16(dst, src) \
    asm volatile("cp.async.cg.shared.global [%0], [%1], 16;" :: "r"(dst), "l"(src))
#define CP_COMMIT() asm volatile("cp.async.commit_group;")
#define CP_WAIT0()  asm volatile("cp.async.wait_group 0;")
#define CP_WAIT1()  asm volatile("cp.async.wait_group 1;")

// D(16x8,f32) += A(16x16 bf16, row) * B(8x16 bf16, "col" = K rows)
#define MMA16816(c, a, b0, b1) \
    asm volatile("mma.sync.aligned.m16n8k16.row.col.f32.bf16.bf16.f32 " \
        "{%0,%1,%2,%3}, {%4,%5,%6,%7}, {%8,%9}, {%0,%1,%2,%3};" \
        : "+f"((c)[0]), "+f"((c)[1]), "+f"((c)[2]), "+f"((c)[3]) \
        : "r"((a)[0]), "r"((a)[1]), "r"((a)[2]), "r"((a)[3]), "r"(b0), "r"(b1))

// ---------------------------------------------------------------------------
// Kernel 1: avAp = a @ ((iswiglu(W@A+b)+eps)^pw) + ba
// ---------------------------------------------------------------------------
__global__ __launch_bounds__(256) void avap_kernel(
    const float* __restrict__ A, const float* __restrict__ W,
    const float* __restrict__ b, const float* __restrict__ pw,
    const float* __restrict__ aM, const float* __restrict__ ba)
{
    float* smem = (float*)dsmem;
    float (*sW)[LDP] = (float (*)[LDP])smem;
    float (*sA)[LDP] = (float (*)[LDP])(smem + DD * LDP);
    float (*sT)[LDP] = (float (*)[LDP])(smem + 2 * DD * LDP);
    const int bh = blockIdx.x, h = bh % HH;
    const int tid = threadIdx.x, ty = tid >> 4, tx = tid & 15;
    const float* Wp = W + h * DD * DD;
    const float* Ap = A + bh * DD * DD;

    for (int i = tid; i < DD * DD; i += 256) {
        int r = i >> 6, c = i & 63;
        sW[r][c] = Wp[i]; sA[r][c] = Ap[i];
    }
    __syncthreads();
    float acc[4][4] = {};
    for (int k = 0; k < DD; k++) {
        float wv[4];
        #pragma unroll
        for (int i = 0; i < 4; i++) wv[i] = sW[ty*4+i][k];
        float4 a4 = *(const float4*)&sA[k][tx*4];
        float av[4] = {a4.x, a4.y, a4.z, a4.w};
        #pragma unroll
        for (int i = 0; i < 4; i++)
            #pragma unroll
            for (int j = 0; j < 4; j++) acc[i][j] = fmaf(wv[i], av[j], acc[i][j]);
    }
    #pragma unroll
    for (int i = 0; i < 4; i++)
        #pragma unroll
        for (int j = 0; j < 4; j++) {
            int r = ty*4+i, c = tx*4+j;
            float x = acc[i][j] + b[h*DD*DD + r*DD + c];
            float sg = 1.0f / (1.0f + __expf(-x));
            float aw = x * x * sg + EPS_ADJ;
            sT[r][c] = __powf(aw, pw[h*DD*DD + r*DD + c]);
        }
    __syncthreads();
    const float* ap2 = aM + h * DD * DD;
    for (int i = tid; i < DD * DD; i += 256) sW[i>>6][i&63] = ap2[i];
    __syncthreads();
    float acc2[4][4] = {};
    for (int k = 0; k < DD; k++) {
        float wv[4];
        #pragma unroll
        for (int i = 0; i < 4; i++) wv[i] = sW[ty*4+i][k];
        float4 t4 = *(const float4*)&sT[k][tx*4];
        float tv[4] = {t4.x, t4.y, t4.z, t4.w};
        #pragma unroll
        for (int i = 0; i < 4; i++)
            #pragma unroll
            for (int j = 0; j < 4; j++) acc2[i][j] = fmaf(wv[i], tv[j], acc2[i][j]);
    }
    #pragma unroll
    for (int i = 0; i < 4; i++)
        #pragma unroll
        for (int j = 0; j < 4; j++) {
            int r = ty*4+i, c = tx*4+j;
            g_avAp[bh*DD*DD + r*DD + c] = acc2[i][j] + ba[h*DD*DD + r*DD + c];
        }
}

// ---------------------------------------------------------------------------
// Kernel 2: K 2-way bf16 split (elementwise, layout preserved)
// ---------------------------------------------------------------------------
__global__ __launch_bounds__(256) void ksplit_kernel(const float* __restrict__ K)
{
    size_t i = (size_t)blockIdx.x * 256 + threadIdx.x;   // float4 index
    float4 v = ((const float4*)K)[i];
    __nv_bfloat16 h0,l0,h1,l1,h2,l2,h3,l3;
    split2(v.x,h0,l0); split2(v.y,h1,l1);
    split2(v.z,h2,l2); split2(v.w,h3,l3);
    ((uint2*)g_Kh)[i] = make_uint2(pack_bf16x2(h0,h1), pack_bf16x2(h2,h3));
    ((uint2*)g_Kl)[i] = make_uint2(pack_bf16x2(l0,l1), pack_bf16x2(l2,l3));
}

// ---------------------------------------------------------------------------
// Kernel 3: V transpose + 2-way bf16 split:  VT[bh][d][s]
// ---------------------------------------------------------------------------
__global__ __launch_bounds__(256) void vprep_kernel(const float* __restrict__ V)
{
    __shared__ float tl[64][65];
    const int st = blockIdx.x, bh = blockIdx.y;
    const int tid = threadIdx.x;
    const float* vp = V + ((size_t)bh * SS + st * 64) * DD;
    for (int i = tid; i < 4096; i += 256) tl[i >> 6][i & 63] = vp[i];
    __syncthreads();
    for (int i = tid; i < 4096; i += 256) {
        int d = i >> 6, s = i & 63;
        __nv_bfloat16 h, l; split2(tl[s][d], h, l);
        size_t o = ((size_t)bh * DD + d) * SS + st * 64 + s;
        g_VTh[o] = h; g_VTl[o] = l;
    }
}

// ---------------------------------------------------------------------------
// Kernel 4: fused flash attention on HMMA, BM=128 rows, 256 thr (8 warps),
// cp.async double-buffered K/V staging. Grid (16 qt, 32 bh).
// smem: Qh,Ql [128][72]bf16 (18432 B x2); 2 stages x (Kh,Kl,Vh,Vl)[64][72]bf16
// ---------------------------------------------------------------------------
#define ROWW 36          // uint32 words per row (72 bf16)
#define QH_OFF 0
#define QL_OFF 18432
#define STG_OFF 36864
#define STG_BYTES 36864  // Kh 9216 | Kl 9216 | Vh 9216 | Vl 9216
#define ATTN_SMEM (STG_OFF + 2*STG_BYTES)   // 110592

__global__ __launch_bounds__(256) void attn_mma_kernel(
    const float* __restrict__ Hin, float* __restrict__ Out)
{
    const int tid  = threadIdx.x;
    const int lane = tid & 31, wid = tid >> 5;
    const int qt = (int)(gridDim.x - 1 - blockIdx.x);   // big tiles first
    const int bh = blockIdx.y;
    const int g  = lane >> 2;       // fragment row within 8
    const int q4 = lane & 3;        // fragment col group
    const uint32_t sbase = smem_to_u32(dsmem);

    uint32_t* wQh = (uint32_t*)(dsmem + QH_OFF);
    uint32_t* wQl = (uint32_t*)(dsmem + QL_OFF);

    // ---- Q = Hin_tile @ avAp (fp32 in stage region), split into wQ ----
    {
        float* fH  = (float*)(dsmem + STG_OFF);            // [128][68]
        float* fAv = (float*)(dsmem + STG_OFF + 34816);    // [64][68]
        for (int i = tid; i < 2048; i += 256) {
            int r = i >> 4, c = (i & 15) << 2;
            *(float4*)&fH[r*68 + c] =
                *(const float4*)&Hin[((size_t)bh*SS + qt*128 + r)*64 + c];
        }
        for (int i = tid; i < 1024; i += 256) {
            int r = i >> 4, c = (i & 15) << 2;
            *(float4*)&fAv[r*68 + c] = *(const float4*)&g_avAp[bh*4096 + r*64 + c];
        }
        __syncthreads();
        const int ty = tid >> 4, tx = tid & 15;   // rows ty*8.., cols tx*4..
        float acc[8][4] = {};
        for (int k = 0; k < 64; k++) {
            float4 av = *(const float4*)&fAv[k*68 + tx*4];
            #pragma unroll
            for (int i = 0; i < 8; i++) {
                float hv = fH[(ty*8+i)*68 + k];
                acc[i][0] = fmaf(hv, av.x, acc[i][0]);
                acc[i][1] = fmaf(hv, av.y, acc[i][1]);
                acc[i][2] = fmaf(hv, av.z, acc[i][2]);
                acc[i][3] = fmaf(hv, av.w, acc[i][3]);
            }
        }
        #pragma unroll
        for (int i = 0; i < 8; i++) {
            int row = ty*8 + i;
            #pragma unroll
            for (int jp = 0; jp < 2; jp++) {
                float v0 = acc[i][jp*2]   * QK_SCALE;
                float v1 = acc[i][jp*2+1] * QK_SCALE;
                __nv_bfloat16 h0,l0,h1,l1;
                split2(v0,h0,l0); split2(v1,h1,l1);
                wQh[row*ROWW + tx*2 + jp] = pack_bf16x2(h0,h1);
                wQl[row*ROWW + tx*2 + jp] = pack_bf16x2(l0,l1);
            }
        }
        __syncthreads();   // stage region free; Q visible
    }

    const int nkt = 2*qt + 2;

    // cp.async staging of one k-tile into stage buffer sb (2048 16B chunks)
    auto stage = [&](int ktt, int sb) {
        uint32_t base = sbase + STG_OFF + sb * STG_BYTES;
        #pragma unroll
        for (int ii = 0; ii < 4; ii++) {          // K: Kh,Kl = 1024 chunks
            int i = ii*256 + tid;
            int a = i >> 9, r = (i >> 3) & 63, c8 = i & 7;
            const __nv_bfloat16* src =
                (a ? g_Kl : g_Kh) + ((size_t)bh*SS + ktt*64 + r)*64 + c8*8;
            CP_ASYNC16(base + a*9216 + r*144 + c8*16, src);
        }
        #pragma unroll
        for (int ii = 0; ii < 4; ii++) {          // V: Vh,Vl = 1024 chunks
            int i = ii*256 + tid;
            int a = i >> 9, d = (i >> 3) & 63, s8 = i & 7;
            const __nv_bfloat16* src =
                (a ? g_VTl : g_VTh) + ((size_t)bh*64 + d)*SS + ktt*64 + s8*8;
            CP_ASYNC16(base + 18432 + a*9216 + d*144 + s8*16, src);
        }
        CP_COMMIT();
    };

    stage(0, 0);
    stage(1, 1);

    float m_run[2] = {-1e30f, -1e30f};
    float l_run[2] = {0.0f, 0.0f};
    float oacc[8][4] = {};
    const int arow = wid*16 + g;

    for (int kt = 0; kt < nkt; kt++) {
        if (kt + 1 < nkt) CP_WAIT1(); else CP_WAIT0();
        __syncthreads();

        const char* stg = dsmem + STG_OFF + (kt & 1) * STG_BYTES;
        const uint32_t* wKh = (const uint32_t*)(stg);
        const uint32_t* wKl = (const uint32_t*)(stg + 9216);
        const uint32_t* wVh = (const uint32_t*)(stg + 18432);
        const uint32_t* wVl = (const uint32_t*)(stg + 27648);

        // lower-half warps fully masked on the final diagonal k-tile: skip
        bool active = !(kt == 2*qt + 1 && wid < 4);
        if (active) {
            // ---- S = Q K^T : combos hh, hl, lh ----
            float sacc[8][4] = {};
            #pragma unroll
            for (int kk = 0; kk < 4; kk++) {
                const int base = kk*8 + q4;
                uint32_t aH[4], aL[4];
                aH[0] = wQh[arow*ROWW + base];      aH[1] = wQh[(arow+8)*ROWW + base];
                aH[2] = wQh[arow*ROWW + base + 4];  aH[3] = wQh[(arow+8)*ROWW + base + 4];
                aL[0] = wQl[arow*ROWW + base];      aL[1] = wQl[(arow+8)*ROWW + base];
                aL[2] = wQl[arow*ROWW + base + 4];  aL[3] = wQl[(arow+8)*ROWW + base + 4];
                #pragma unroll
                for (int n = 0; n < 8; n++) {
                    const int brow = n*8 + g;
                    uint32_t bH0 = wKh[brow*ROWW + base], bH1 = wKh[brow*ROWW + base + 4];
                    uint32_t bL0 = wKl[brow*ROWW + base], bL1 = wKl[brow*ROWW + base + 4];
                    MMA16816(sacc[n], aH, bH0, bH1);
                    MMA16816(sacc[n], aH, bL0, bL1);
                    MMA16816(sacc[n], aL, bH0, bH1);
                }
            }

            // ---- causal mask (only near-diagonal k-tiles) ----
            if (kt >= 2*qt) {
                #pragma unroll
                for (int n = 0; n < 8; n++)
                    #pragma unroll
                    for (int c = 0; c < 4; c++) {
                        int col = kt*64 + n*8 + q4*2 + (c & 1);
                        int row = qt*128 + wid*16 + g + ((c >> 1) << 3);
                        if (col > row) sacc[n][c] = -1e30f;
                    }
            }

            // ---- online softmax ----
            float mt0 = -1e30f, mt1 = -1e30f;
            #pragma unroll
            for (int n = 0; n < 8; n++) {
                mt0 = fmaxf(mt0, fmaxf(sacc[n][0], sacc[n][1]));
                mt1 = fmaxf(mt1, fmaxf(sacc[n][2], sacc[n][3]));
            }
            mt0 = fmaxf(mt0, __shfl_xor_sync(0xFFFFFFFFu, mt0, 1));
            mt0 = fmaxf(mt0, __shfl_xor_sync(0xFFFFFFFFu, mt0, 2));
            mt1 = fmaxf(mt1, __shfl_xor_sync(0xFFFFFFFFu, mt1, 1));
            mt1 = fmaxf(mt1, __shfl_xor_sync(0xFFFFFFFFu, mt1, 2));
            float mN0 = fmaxf(m_run[0], mt0), mN1 = fmaxf(m_run[1], mt1);
            float al0 = ex2f(m_run[0] - mN0), al1 = ex2f(m_run[1] - mN1);
            m_run[0] = mN0; m_run[1] = mN1;

            float ls0 = 0.0f, ls1 = 0.0f;
            #pragma unroll
            for (int n = 0; n < 8; n++) {
                float p0 = ex2f(sacc[n][0] - mN0);
                float p1 = ex2f(sacc[n][1] - mN0);
                float p2 = ex2f(sacc[n][2] - mN1);
                float p3 = ex2f(sacc[n][3] - mN1);
                sacc[n][0] = p0; sacc[n][1] = p1; sacc[n][2] = p2; sacc[n][3] = p3;
                ls0 += p0 + p1; ls1 += p2 + p3;
                oacc[n][0] *= al0; oacc[n][1] *= al0;
                oacc[n][2] *= al1; oacc[n][3] *= al1;
            }
            l_run[0] = l_run[0]*al0 + ls0;
            l_run[1] = l_run[1]*al1 + ls1;

            // ---- O += P V : combos hh, hl, lh (P repacked in-register) ----
            #pragma unroll
            for (int kk = 0; kk < 4; kk++) {
                uint32_t aH[4], aL[4];
                #pragma unroll
                for (int t = 0; t < 2; t++) {
                    int nn = 2*kk + t;
                    __nv_bfloat16 h0,l0,h1,l1;
                    split2(sacc[nn][0], h0,l0); split2(sacc[nn][1], h1,l1);
                    aH[2*t]   = pack_bf16x2(h0,h1); aL[2*t]   = pack_bf16x2(l0,l1);
                    split2(sacc[nn][2], h0,l0); split2(sacc[nn][3], h1,l1);
                    aH[2*t+1] = pack_bf16x2(h0,h1); aL[2*t+1] = pack_bf16x2(l0,l1);
                }
                const int base = kk*8 + q4;
                #pragma unroll
                for (int n = 0; n < 8; n++) {
                    const int brow = n*8 + g;
                    uint32_t bH0 = wVh[brow*ROWW + base], bH1 = wVh[brow*ROWW + base + 4];
                    uint32_t bL0 = wVl[brow*ROWW + base], bL1 = wVl[brow*ROWW + base + 4];
                    MMA16816(oacc[n], aH, bH0, bH1);
                    MMA16816(oacc[n], aH, bL0, bL1);
                    MMA16816(oacc[n], aL, bH0, bH1);
                }
            }
        }
        __syncthreads();          // all reads of this stage done
        if (kt + 2 < nkt) stage(kt + 2, kt & 1);
    }

    // ---- epilogue ----
    float lt0 = l_run[0];
    lt0 += __shfl_xor_sync(0xFFFFFFFFu, lt0, 1);
    lt0 += __shfl_xor_sync(0xFFFFFFFFu, lt0, 2);
    float lt1 = l_run[1];
    lt1 += __shfl_xor_sync(0xFFFFFFFFu, lt1, 1);
    lt1 += __shfl_xor_sync(0xFFFFFFFFu, lt1, 2);
    float inv0 = 1.0f / lt0, inv1 = 1.0f / lt1;

    const int row0 = qt*128 + wid*16 + g;
    const int row1 = row0 + 8;
    #pragma unroll
    for (int n = 0; n < 8; n++) {
        int col = n*8 + q4*2;
        float2 o0 = make_float2(oacc[n][0]*inv0, oacc[n][1]*inv0);
        float2 o1 = make_float2(oacc[n][2]*inv1, oacc[n][3]*inv1);
        *(float2*)&Out[((size_t)bh*SS + row0)*64 + col] = o0;
        *(float2*)&Out[((size_t)bh*SS + row1)*64 + col] = o1;
    }
}

// ---------------------------------------------------------------------------
extern "C" void kernel_launch(void* const* d_in, const int* in_sizes, int n_in,
                              void* d_out, int out_size)
{
    const float* Hin = (const float*)d_in[0];
    const float* Hk  = (const float*)d_in[1];
    const float* Hv  = (const float*)d_in[2];
    const float* A   = (const float*)d_in[3];
    // d_in[4] = mask (causal, analytic)
    const float* W   = (const float*)d_in[5];
    const float* b   = (const float*)d_in[6];
    const float* pw  = (const float*)d_in[7];
    const float* aM  = (const float*)d_in[8];
    const float* ba  = (const float*)d_in[9];
    float* Out = (float*)d_out;

    const int smem1 = 3 * DD * LDP * sizeof(float);   // 52224
    cudaFuncSetAttribute(avap_kernel, cudaFuncAttributeMaxDynamicSharedMemorySize, smem1);
    cudaFuncSetAttribute(attn_mma_kernel, cudaFuncAttributeMaxDynamicSharedMemorySize, ATTN_SMEM);

    avap_kernel<<<BH, 256, smem1>>>(A, W, b, pw, aM, ba);
    ksplit_kernel<<<(BH * SS * DD) / 4 / 256, 256>>>(Hk);
    vprep_kernel<<<dim3(SS / 64, BH), 256>>>(Hv);
    attn_mma_kernel<<<dim3(SS / 128, BH), 256, ATTN_SMEM>>>(Hin, Out);
}